// round 6
// baseline (speedup 1.0000x reference)
#include <cuda_runtime.h>
#include <math.h>

#define B_   16
#define C_   256
#define H_   32
#define W_   32
#define HW   1024
#define HM   128
#define WM   128
#define HWM  16384
#define N_   100
#define F_   1024
#define NH_  8
#define HD   32
#define L_   2
#define EPSF 1e-5f

#define OUT_Q     0
#define OUT_PRED  (B_*N_*C_)
#define OUT_INTER (OUT_PRED + B_*N_*HWM)

#define OFF_Q    0L
#define OFF_E1   409600L
#define OFF_E    819200L
#define OFF_QB   1228800L
#define OFF_OB   1638400L
#define OFF_TMP  2048000L
#define OFF_FFH  2457600L
#define OFF_FE   4096000L
#define OFF_KB   8290304L
#define OFF_VB   12484608L
#define SCRATCH_FLOATS (12484608L + 4194304L)

__device__ float g_scratch[SCRATCH_FLOATS];
__device__ unsigned char g_am[B_ * N_ * HW];

// cvt.rna.tf32.f32 requires a b32 destination register; result is an
// fp32-layout bit pattern with the low 13 mantissa bits zeroed.
__device__ __forceinline__ unsigned tf32_rna_bits(float x) {
    unsigned r;
    asm("cvt.rna.tf32.f32 %0, %1;" : "=r"(r) : "f"(x));
    return r;
}

__device__ __forceinline__ void mma_tf32(float c[4],
                                         float a0, float a1, float a2, float a3,
                                         float b0, float b1)
{
    asm volatile(
        "mma.sync.aligned.m16n8k8.row.col.f32.tf32.tf32.f32 "
        "{%0,%1,%2,%3}, {%4,%5,%6,%7}, {%8,%9}, {%0,%1,%2,%3};"
        : "+f"(c[0]), "+f"(c[1]), "+f"(c[2]), "+f"(c[3])
        : "r"(__float_as_uint(a0)), "r"(__float_as_uint(a1)),
          "r"(__float_as_uint(a2)), "r"(__float_as_uint(a3)),
          "r"(__float_as_uint(b0)), "r"(__float_as_uint(b1)));
}

// ============================================================
// gemm_tf32: 128x128 tile, BK=16, 3-term TF32 split (~fp32 acc).
// mma.m16n8k8; warps 4(m)x2(n), warp tile 32x64.
// Requires N%128==0, K%16==0. M guarded.
// ============================================================
__global__ void __launch_bounds__(256, 2)
gemm_tf32(const float* __restrict__ A, const float* __restrict__ B,
          const float* __restrict__ bias, float* __restrict__ C,
          int M, int N, int K, int relu, long sA, long sB, long sC)
{
    __shared__ float Ah[128][20], Al[128][20];
    __shared__ float Bh[16][136],  Bl[16][136];

    long bz = blockIdx.z;
    A += bz * sA;  B += bz * sB;  C += bz * sC;

    int tid = threadIdx.x;
    int m0 = blockIdx.y * 128, n0 = blockIdx.x * 128;
    int w = tid >> 5, lane = tid & 31;
    int wm = (w & 3) * 32, wn = (w >> 2) * 64;
    int lr = lane >> 2, lc = lane & 3;

    int ar  = tid >> 1, akh = (tid & 1) * 8;   // A: 128 rows x 16 k
    int bk  = tid >> 4, bn  = (tid & 15) * 8;  // B: 16 k x 128 n

    bool arow_ok = (m0 + ar) < M;
    const float* Aptr = A + (long)(m0 + ar) * K + akh;
    const float* Bptr = B + (long)bk * N + n0 + bn;

    float acc[2][8][4];
#pragma unroll
    for (int mt = 0; mt < 2; mt++)
#pragma unroll
        for (int nt = 0; nt < 8; nt++)
#pragma unroll
            for (int i = 0; i < 4; i++) acc[mt][nt][i] = 0.f;

    float4 av0 = make_float4(0.f,0.f,0.f,0.f), av1 = av0, bv0, bv1;
    if (arow_ok) { av0 = *(const float4*)Aptr; av1 = *(const float4*)(Aptr + 4); }
    bv0 = *(const float4*)Bptr; bv1 = *(const float4*)(Bptr + 4);

    int NT = K / 16;
    for (int t = 0; t < NT; t++) {
        {
            float a[8] = {av0.x, av0.y, av0.z, av0.w, av1.x, av1.y, av1.z, av1.w};
#pragma unroll
            for (int j = 0; j < 8; j++) {
                float hi = __uint_as_float(tf32_rna_bits(a[j]));
                Ah[ar][akh + j] = hi;
                Al[ar][akh + j] = __uint_as_float(tf32_rna_bits(a[j] - hi));
            }
            float b[8] = {bv0.x, bv0.y, bv0.z, bv0.w, bv1.x, bv1.y, bv1.z, bv1.w};
#pragma unroll
            for (int j = 0; j < 8; j++) {
                float hi = __uint_as_float(tf32_rna_bits(b[j]));
                Bh[bk][bn + j] = hi;
                Bl[bk][bn + j] = __uint_as_float(tf32_rna_bits(b[j] - hi));
            }
        }
        __syncthreads();

        if (t + 1 < NT) {
            const float* Ap = Aptr + (t + 1) * 16;
            if (arow_ok) { av0 = *(const float4*)Ap; av1 = *(const float4*)(Ap + 4); }
            const float* Bp = Bptr + (long)(t + 1) * 16 * N;
            bv0 = *(const float4*)Bp; bv1 = *(const float4*)(Bp + 4);
        }

#pragma unroll
        for (int kk = 0; kk < 16; kk += 8) {
            float ah[2][4], al[2][4];
#pragma unroll
            for (int mt = 0; mt < 2; mt++) {
                int mr = wm + mt * 16 + lr;
                ah[mt][0] = Ah[mr][kk + lc];     ah[mt][1] = Ah[mr + 8][kk + lc];
                ah[mt][2] = Ah[mr][kk + lc + 4]; ah[mt][3] = Ah[mr + 8][kk + lc + 4];
                al[mt][0] = Al[mr][kk + lc];     al[mt][1] = Al[mr + 8][kk + lc];
                al[mt][2] = Al[mr][kk + lc + 4]; al[mt][3] = Al[mr + 8][kk + lc + 4];
            }
#pragma unroll
            for (int nt = 0; nt < 8; nt++) {
                int nc = wn + nt * 8 + lr;
                float bh0 = Bh[kk + lc][nc],     bh1 = Bh[kk + lc + 4][nc];
                float bl0 = Bl[kk + lc][nc],     bl1 = Bl[kk + lc + 4][nc];
#pragma unroll
                for (int mt = 0; mt < 2; mt++) {
                    mma_tf32(acc[mt][nt], ah[mt][0], ah[mt][1], ah[mt][2], ah[mt][3], bh0, bh1);
                    mma_tf32(acc[mt][nt], ah[mt][0], ah[mt][1], ah[mt][2], ah[mt][3], bl0, bl1);
                    mma_tf32(acc[mt][nt], al[mt][0], al[mt][1], al[mt][2], al[mt][3], bh0, bh1);
                }
            }
        }
        __syncthreads();
    }

#pragma unroll
    for (int mt = 0; mt < 2; mt++) {
#pragma unroll
        for (int nt = 0; nt < 8; nt++) {
            int row = m0 + wm + mt * 16 + lr;
            int col = n0 + wn + nt * 8 + lc * 2;
            float bx = 0.f, by = 0.f;
            if (bias) { bx = bias[col]; by = bias[col + 1]; }
            float2 v0, v1;
            v0.x = acc[mt][nt][0] + bx; v0.y = acc[mt][nt][1] + by;
            v1.x = acc[mt][nt][2] + bx; v1.y = acc[mt][nt][3] + by;
            if (relu) {
                v0.x = fmaxf(v0.x, 0.f); v0.y = fmaxf(v0.y, 0.f);
                v1.x = fmaxf(v1.x, 0.f); v1.y = fmaxf(v1.y, 0.f);
            }
            if (row < M)     *(float2*)(C + (long)row * N + col)       = v0;
            if (row + 8 < M) *(float2*)(C + (long)(row + 8) * N + col) = v1;
        }
    }
}

// ============================================================
// gemm64: 64x64 tile, BK=16, 256 thr, 4x4/thread. For small GEMMs.
// ============================================================
__global__ void gemm64(const float* __restrict__ A, const float* __restrict__ B,
                       const float* __restrict__ bias, float* __restrict__ C,
                       int M, int N, int K, int relu,
                       long sA, long sB, long sC)
{
    const int BM = 64, BN = 64, BK = 16;
    __shared__ float As[BK][BM + 4];
    __shared__ float Bs[BK][BN];

    long bz = blockIdx.z;
    A += bz * sA;  B += bz * sB;  C += bz * sC;

    int tid = threadIdx.x;
    int brow = blockIdx.y * BM;
    int bcol = blockIdx.x * BN;
    int tx = tid & 15, ty = tid >> 4;

    int arow = tid >> 2;
    int ak   = (tid & 3) * 4;
    int bro  = tid >> 4;
    int bco  = (tid & 15) * 4;

    float acc[4][4];
#pragma unroll
    for (int i = 0; i < 4; i++)
#pragma unroll
        for (int j = 0; j < 4; j++) acc[i][j] = 0.f;

    for (int k0 = 0; k0 < K; k0 += BK) {
        float4 av;
        if (brow + arow < M)
            av = *(const float4*)(A + (long)(brow + arow) * K + k0 + ak);
        else
            av = make_float4(0.f, 0.f, 0.f, 0.f);
        As[ak + 0][arow] = av.x;
        As[ak + 1][arow] = av.y;
        As[ak + 2][arow] = av.z;
        As[ak + 3][arow] = av.w;

        float4 bv = *(const float4*)(B + (long)(k0 + bro) * N + bcol + bco);
        *(float4*)&Bs[bro][bco] = bv;
        __syncthreads();

#pragma unroll
        for (int kk = 0; kk < BK; kk++) {
            float ra[4], rb[4];
#pragma unroll
            for (int i = 0; i < 4; i++) ra[i] = As[kk][ty * 4 + i];
#pragma unroll
            for (int j = 0; j < 4; j++) rb[j] = Bs[kk][tx * 4 + j];
#pragma unroll
            for (int i = 0; i < 4; i++)
#pragma unroll
                for (int j = 0; j < 4; j++)
                    acc[i][j] += ra[i] * rb[j];
        }
        __syncthreads();
    }

#pragma unroll
    for (int i = 0; i < 4; i++) {
        int r = brow + ty * 4 + i;
        if (r >= M) continue;
#pragma unroll
        for (int j = 0; j < 4; j++) {
            int c = bcol + tx * 4 + j;
            float v = acc[i][j];
            if (bias) v += bias[c];
            if (relu) v = fmaxf(v, 0.f);
            C[(long)r * N + c] = v;
        }
    }
}

// ============================================================
// feats transpose: (B, C, HW) -> (B, HW, C)
// ============================================================
__global__ void feats_transpose(const float* __restrict__ feat, float* __restrict__ out)
{
    __shared__ float tile[32][33];
    int b  = blockIdx.z;
    int c0 = blockIdx.x * 32;
    int s0 = blockIdx.y * 32;
    int tx = threadIdx.x, ty = threadIdx.y;
#pragma unroll
    for (int i = 0; i < 32; i += 8)
        tile[ty + i][tx] = feat[((long)b * C_ + c0 + ty + i) * HW + s0 + tx];
    __syncthreads();
#pragma unroll
    for (int i = 0; i < 32; i += 8)
        out[((long)b * HW + s0 + ty + i) * C_ + c0 + tx] = tile[tx][ty + i];
}

__global__ void bcast_queries(const float* __restrict__ qe, float* __restrict__ q)
{
    int i = blockIdx.x * blockDim.x + threadIdx.x;
    if (i < B_ * N_ * C_) q[i] = qe[i % (N_ * C_)];
}

// ============================================================
// attention mask from cur
// ============================================================
__global__ void mask_kernel(const float* __restrict__ cur, unsigned char* __restrict__ am)
{
    int row = blockIdx.x;
    int t = threadIdx.x;
    int y = t >> 5, x = t & 31;
    const float* p = cur + (long)row * HWM;
    int r0 = 4 * y + 1, c0 = 4 * x + 1;
    float v00 = p[r0 * WM + c0],       v01 = p[r0 * WM + c0 + 1];
    float v10 = p[(r0 + 1) * WM + c0], v11 = p[(r0 + 1) * WM + c0 + 1];
    float s = 1.f / (1.f + expf(-v00)) + 1.f / (1.f + expf(-v01))
            + 1.f / (1.f + expf(-v10)) + 1.f / (1.f + expf(-v11));
    int m = (0.25f * s) > 0.5f;

    __shared__ int cnt[32];
    unsigned bal = __ballot_sync(0xffffffffu, m);
    if ((t & 31) == 0) cnt[t >> 5] = __popc(bal);
    __syncthreads();
    if (t < 32) {
        int v = cnt[t];
#pragma unroll
        for (int o = 16; o > 0; o >>= 1) v += __shfl_down_sync(0xffffffffu, v, o);
        if (t == 0) cnt[0] = v;
    }
    __syncthreads();
    am[(long)row * HW + t] = (cnt[0] == 0) ? (unsigned char)1 : (unsigned char)m;
}

// ============================================================
// attention v2 (dynamic smem): block per (h, b); flash-style.
// ============================================================
struct AttnSmem {
    float Ks[128][36];
    float Vs[128][36];
    float qsm[N_][32];
    float psm[8][4][128];
};

extern __shared__ char attn_smem_raw[];

__global__ void __launch_bounds__(256)
attn2(const float* __restrict__ Q, const float* __restrict__ K,
      const float* __restrict__ V, const unsigned char* __restrict__ am,
      float* __restrict__ O)
{
    AttnSmem& sm = *reinterpret_cast<AttnSmem*>(attn_smem_raw);
    int h = blockIdx.x, b = blockIdx.y;

    int tid = threadIdx.x, w = tid >> 5, lane = tid & 31;

    for (int n = w; n < N_; n += 8)
        sm.qsm[n][lane] = Q[((long)(b * N_ + n)) * C_ + h * HD + lane];

    float m[4][4], su[4][4], oa[4][4];
#pragma unroll
    for (int t = 0; t < 4; t++)
#pragma unroll
        for (int qq = 0; qq < 4; qq++) { m[t][qq] = -1e30f; su[t][qq] = 0.f; oa[t][qq] = 0.f; }

    const unsigned char* amb = am + (long)b * N_ * HW;
    const float scale = 0.17677669529663687f;

    for (int c0 = 0; c0 < HW; c0 += 128) {
        __syncthreads();
#pragma unroll
        for (int it = 0; it < 4; it++) {
            int i = tid + it * 256;
            int r = i >> 3, d4 = (i & 7) * 4;
            float4 kv = *(const float4*)(K + ((long)(b * HW + c0 + r)) * C_ + h * HD + d4);
            *(float4*)&sm.Ks[r][d4] = kv;
            float4 vv = *(const float4*)(V + ((long)(b * HW + c0 + r)) * C_ + h * HD + d4);
            *(float4*)&sm.Vs[r][d4] = vv;
        }
        __syncthreads();

#pragma unroll
        for (int t = 0; t < 4; t++) {
            int g = w + 8 * t;
            if (g >= 25) break;

            float dacc[4][4];
#pragma unroll
            for (int qq = 0; qq < 4; qq++)
#pragma unroll
                for (int i = 0; i < 4; i++) dacc[qq][i] = 0.f;

#pragma unroll
            for (int dd4 = 0; dd4 < 8; dd4++) {
                float4 k4[4];
#pragma unroll
                for (int i = 0; i < 4; i++)
                    k4[i] = *(const float4*)&sm.Ks[i * 32 + lane][dd4 * 4];
#pragma unroll
                for (int qq = 0; qq < 4; qq++) {
                    float4 q4 = *(const float4*)&sm.qsm[g * 4 + qq][dd4 * 4];
#pragma unroll
                    for (int i = 0; i < 4; i++)
                        dacc[qq][i] += q4.x*k4[i].x + q4.y*k4[i].y + q4.z*k4[i].z + q4.w*k4[i].w;
                }
            }

            __syncwarp();
#pragma unroll
            for (int qq = 0; qq < 4; qq++) {
                int q = g * 4 + qq;
                const unsigned char* amp = amb + (long)q * HW + c0;
                float sc[4];
#pragma unroll
                for (int i = 0; i < 4; i++) {
                    int s = i * 32 + lane;
                    sc[i] = amp[s] ? dacc[qq][i] * scale : -1e30f;
                }
                float cmax = fmaxf(fmaxf(sc[0], sc[1]), fmaxf(sc[2], sc[3]));
#pragma unroll
                for (int o = 16; o > 0; o >>= 1)
                    cmax = fmaxf(cmax, __shfl_xor_sync(0xffffffffu, cmax, o));
                float nm = fmaxf(m[t][qq], cmax);
                float p[4], ls = 0.f;
#pragma unroll
                for (int i = 0; i < 4; i++) {
                    p[i] = (sc[i] < -1e29f) ? 0.f : __expf(sc[i] - nm);
                    ls += p[i];
                }
#pragma unroll
                for (int o = 16; o > 0; o >>= 1)
                    ls += __shfl_xor_sync(0xffffffffu, ls, o);
                float alpha = __expf(m[t][qq] - nm);
                su[t][qq] = su[t][qq] * alpha + ls;
                oa[t][qq] *= alpha;
                m[t][qq] = nm;
#pragma unroll
                for (int i = 0; i < 4; i++)
                    sm.psm[w][qq][i * 32 + lane] = p[i];
            }
            __syncwarp();

            float po[4] = {0.f, 0.f, 0.f, 0.f};
#pragma unroll
            for (int s4 = 0; s4 < 32; s4++) {
                float v0 = sm.Vs[s4 * 4 + 0][lane];
                float v1 = sm.Vs[s4 * 4 + 1][lane];
                float v2 = sm.Vs[s4 * 4 + 2][lane];
                float v3 = sm.Vs[s4 * 4 + 3][lane];
#pragma unroll
                for (int qq = 0; qq < 4; qq++) {
                    float4 p4 = *(const float4*)&sm.psm[w][qq][s4 * 4];
                    po[qq] += p4.x * v0 + p4.y * v1 + p4.z * v2 + p4.w * v3;
                }
            }
#pragma unroll
            for (int qq = 0; qq < 4; qq++) oa[t][qq] += po[qq];
            __syncwarp();
        }
    }

#pragma unroll
    for (int t = 0; t < 4; t++) {
        int g = w + 8 * t;
        if (g >= 25) break;
#pragma unroll
        for (int qq = 0; qq < 4; qq++)
            O[((long)(b * N_ + g * 4 + qq)) * C_ + h * HD + lane] = oa[t][qq] / su[t][qq];
    }
}

// ============================================================
// LayerNorm over C=256, optional residual
// ============================================================
__global__ void ln_kernel(const float* __restrict__ X, const float* __restrict__ R,
                          const float* __restrict__ g, const float* __restrict__ be,
                          float* __restrict__ Y)
{
    int row = blockIdx.x;
    int t = threadIdx.x;
    float x = X[(long)row * C_ + t];
    if (R) x += R[(long)row * C_ + t];

    __shared__ float red[8];
    float s = x;
#pragma unroll
    for (int o = 16; o > 0; o >>= 1) s += __shfl_xor_sync(0xffffffffu, s, o);
    if ((t & 31) == 0) red[t >> 5] = s;
    __syncthreads();
    if (t < 8) {
        float v = red[t];
#pragma unroll
        for (int o = 4; o > 0; o >>= 1) v += __shfl_xor_sync(0xffu, v, o);
        if (t == 0) red[0] = v;
    }
    __syncthreads();
    float mean = red[0] * (1.f / C_);
    float dv = x - mean;
    float s2 = dv * dv;
    __syncthreads();
#pragma unroll
    for (int o = 16; o > 0; o >>= 1) s2 += __shfl_xor_sync(0xffffffffu, s2, o);
    if ((t & 31) == 0) red[t >> 5] = s2;
    __syncthreads();
    if (t < 8) {
        float v = red[t];
#pragma unroll
        for (int o = 4; o > 0; o >>= 1) v += __shfl_xor_sync(0xffu, v, o);
        if (t == 0) red[0] = v;
    }
    __syncthreads();
    float var = red[0] * (1.f / C_);
    Y[(long)row * C_ + t] = dv * rsqrtf(var + EPSF) * g[t] + be[t];
}

// ============================================================
// host orchestration
// ============================================================
extern "C" void kernel_launch(void* const* d_in, const int* in_sizes, int n_in,
                              void* d_out, int out_size)
{
    (void)in_sizes; (void)n_in; (void)out_size;
    const float* features      = (const float*)d_in[0];
    const float* mask_features = (const float*)d_in[1];
    const float* query_embed   = (const float*)d_in[2];
    const float* Wq  = (const float*)d_in[3];
    const float* bq  = (const float*)d_in[4];
    const float* Wk  = (const float*)d_in[5];
    const float* bk  = (const float*)d_in[6];
    const float* Wv  = (const float*)d_in[7];
    const float* bv  = (const float*)d_in[8];
    const float* Wo  = (const float*)d_in[9];
    const float* bo  = (const float*)d_in[10];
    const float* g1  = (const float*)d_in[11];
    const float* be1 = (const float*)d_in[12];
    const float* W1  = (const float*)d_in[13];
    const float* b1  = (const float*)d_in[14];
    const float* W2  = (const float*)d_in[15];
    const float* b2  = (const float*)d_in[16];
    const float* g2  = (const float*)d_in[17];
    const float* be2 = (const float*)d_in[18];
    const float* gN  = (const float*)d_in[19];
    const float* beN = (const float*)d_in[20];
    const float* Wm1 = (const float*)d_in[21];
    const float* bm1 = (const float*)d_in[22];
    const float* Wm2 = (const float*)d_in[23];
    const float* bm2 = (const float*)d_in[24];
    float* out = (float*)d_out;

    float* S; cudaGetSymbolAddress((void**)&S, g_scratch);
    unsigned char* AM; cudaGetSymbolAddress((void**)&AM, g_am);

    cudaFuncSetAttribute(attn2, cudaFuncAttributeMaxDynamicSharedMemorySize,
                         (int)sizeof(AttnSmem));

    float* Qcur = S + OFF_Q;
    float* E1   = S + OFF_E1;
    float* E    = S + OFF_E;
    float* QB   = S + OFF_QB;
    float* OB   = S + OFF_OB;
    float* TMP  = S + OFF_TMP;
    float* FFH  = S + OFF_FFH;
    float* FE   = S + OFF_FE;
    float* KB   = S + OFF_KB;
    float* VB   = S + OFF_VB;

    const int MQ = B_ * N_;   // 1600

    feats_transpose<<<dim3(C_ / 32, HW / 32, B_), dim3(32, 8)>>>(features, FE);
    bcast_queries<<<(B_ * N_ * C_ + 255) / 256, 256>>>(query_embed, Qcur);

    for (int l = 0; l < L_; l++) {
        gemm64<<<dim3(C_ / 64, 25, 1), 256>>>(Qcur, Wm1, bm1, E1, MQ, C_, C_, 1, 0, 0, 0);
        gemm64<<<dim3(C_ / 64, 25, 1), 256>>>(E1, Wm2, bm2, E, MQ, C_, C_, 0, 0, 0, 0);
        float* curp = out + OUT_INTER + (long)l * B_ * N_ * HWM;
        gemm_tf32<<<dim3(HWM / 128, 1, B_), 256>>>(E, mask_features, nullptr, curp,
                                                   N_, HWM, C_, 0,
                                                   (long)N_ * C_, (long)C_ * HWM, (long)N_ * HWM);
        mask_kernel<<<MQ, 1024>>>(curp, AM);

        gemm64<<<dim3(C_ / 64, 25, 1), 256>>>(Qcur, Wq + (long)l * C_ * C_, bq + l * C_,
                                              QB, MQ, C_, C_, 0, 0, 0, 0);
        gemm_tf32<<<dim3(C_ / 128, HW * B_ / 128, 1), 256>>>(FE, Wk + (long)l * C_ * C_, bk + l * C_,
                                                             KB, B_ * HW, C_, C_, 0, 0, 0, 0);
        gemm_tf32<<<dim3(C_ / 128, HW * B_ / 128, 1), 256>>>(FE, Wv + (long)l * C_ * C_, bv + l * C_,
                                                             VB, B_ * HW, C_, C_, 0, 0, 0, 0);

        attn2<<<dim3(NH_, B_), 256, sizeof(AttnSmem)>>>(QB, KB, VB, AM, OB);

        gemm64<<<dim3(C_ / 64, 25, 1), 256>>>(OB, Wo + (long)l * C_ * C_, bo + l * C_,
                                              TMP, MQ, C_, C_, 0, 0, 0, 0);
        ln_kernel<<<MQ, C_>>>(Qcur, TMP, g1 + l * C_, be1 + l * C_, Qcur);

        gemm_tf32<<<dim3(F_ / 128, (MQ + 127) / 128, 1), 256>>>(Qcur, W1 + (long)l * C_ * F_, b1 + l * F_,
                                                                FFH, MQ, F_, C_, 1, 0, 0, 0);
        gemm64<<<dim3(C_ / 64, 25, 1), 256>>>(FFH, W2 + (long)l * F_ * C_, b2 + l * C_,
                                              TMP, MQ, C_, F_, 0, 0, 0, 0);
        ln_kernel<<<MQ, C_>>>(Qcur, TMP, g2 + l * C_, be2 + l * C_, Qcur);
    }

    ln_kernel<<<MQ, C_>>>(Qcur, nullptr, gN, beN, out + OUT_Q);

    gemm64<<<dim3(C_ / 64, 25, 1), 256>>>(out + OUT_Q, Wm1, bm1, E1, MQ, C_, C_, 1, 0, 0, 0);
    gemm64<<<dim3(C_ / 64, 25, 1), 256>>>(E1, Wm2, bm2, E, MQ, C_, C_, 0, 0, 0, 0);
    gemm_tf32<<<dim3(HWM / 128, 1, B_), 256>>>(E, mask_features, nullptr, out + OUT_PRED,
                                               N_, HWM, C_, 0,
                                               (long)N_ * C_, (long)C_ * HWM, (long)N_ * HWM);
}